// round 14
// baseline (speedup 1.0000x reference)
#include <cuda_runtime.h>
#include <cuda_fp16.h>
#include <cstdint>

#define B_DIM 16
#define S_DIM 2048
#define I_DIM 1024
#define H_DIM 1024
#define M_TOTAL (B_DIM * S_DIM)   // 32768

#define BM 256
#define BN 128
#define KIT 32                    // K tiles of 32 halves each
#define THREADS 544               // 16 consumer warps + 1 producer warp
#define STAGE_BYTES 24576         // A: 256x64B (16KB) + B: 128x64B (8KB)
#define STAGE_U32 6144
#define SMEM_BYTES (128 + 4 * STAGE_BYTES)   // mbarriers + 4 stages = 98432

// Pre-permuted half buffers: row r, k-block kb (32 halves = 16 pairs),
// pair q at u32 position P(q) = 4*(q&3) + (q>>2) within the 16-u32 block.
// Lane tg LDS.128 at offset 4*tg -> pairs {tg, tg+4, tg+8, tg+12} =
// the m16n8k16 A/B fragments for both k-steps.
__device__ uint32_t g_xh[(size_t)M_TOTAL * I_DIM / 2];   // 64 MB
__device__ uint32_t g_wh[(size_t)H_DIM * I_DIM / 2];     // 2 MB
__device__ float    g_hterm[B_DIM * H_DIM];

// ---------------- helpers ----------------
__device__ __forceinline__ uint32_t smem_u32(const void* p) {
    uint32_t a;
    asm("{ .reg .u64 t; cvta.to.shared.u64 t, %1; cvt.u32.u64 %0, t; }" : "=r"(a) : "l"(p));
    return a;
}

__device__ __forceinline__ float tanh_fast(float v) {
    float e, r;
    asm("ex2.approx.f32 %0, %1;" : "=f"(e) : "f"(v * 2.8853900817779268f));
    asm("rcp.approx.f32 %0, %1;" : "=f"(r) : "f"(e + 1.0f));
    return fmaf(-2.0f, r, 1.0f);
}

__device__ __forceinline__ uint32_t pack_h2(float lo, float hi) {
    uint32_t r;
    asm("cvt.rn.f16x2.f32 %0, %1, %2;" : "=r"(r) : "f"(hi), "f"(lo));
    return r;
}

__device__ __forceinline__ void mma16816(float* d,
                                         uint32_t a0, uint32_t a1, uint32_t a2, uint32_t a3,
                                         uint32_t b0, uint32_t b1) {
    asm("mma.sync.aligned.m16n8k16.row.col.f32.f16.f16.f32 "
        "{%0,%1,%2,%3}, {%4,%5,%6,%7}, {%8,%9}, {%0,%1,%2,%3};"
        : "+f"(d[0]), "+f"(d[1]), "+f"(d[2]), "+f"(d[3])
        : "r"(a0), "r"(a1), "r"(a2), "r"(a3), "r"(b0), "r"(b1));
}

#define CP16(dst, src) \
    asm volatile("cp.async.cg.shared.global [%0], [%1], 16;" :: "r"(dst), "l"(src) : "memory")
#define CP_COMMIT() asm volatile("cp.async.commit_group;" ::: "memory")
#define CP_WAITG(n) asm volatile("cp.async.wait_group %0;" :: "n"(n) : "memory")
#define MBARRIER_INIT(addr, cnt) \
    asm volatile("mbarrier.init.shared.b64 [%0], %1;" :: "r"(addr), "r"(cnt) : "memory")
#define MBARRIER_ARRIVE(addr) \
    asm volatile("mbarrier.arrive.shared.b64 _, [%0];" :: "r"(addr) : "memory")
#define MBARRIER_WAIT_PARITY(addr, par) do {                                     \
    uint32_t _m = (addr), _p = (par), _done;                                     \
    asm volatile("{\n\t.reg .pred p;\n\t"                                        \
        "mbarrier.try_wait.parity.shared.b64 p, [%1], %2;\n\t"                   \
        "selp.b32 %0, 1, 0, p;\n\t}" : "=r"(_done) : "r"(_m), "r"(_p) : "memory"); \
    if (!_done) {                                                                \
        asm volatile("{\n\t.reg .pred P1;\n\t"                                   \
            "WL_%=:\n\t"                                                         \
            "mbarrier.try_wait.parity.shared.b64 P1, [%0], %1;\n\t"              \
            "@P1 bra.uni WD_%=;\n\t"                                             \
            "bra.uni WL_%=;\n\t"                                                 \
            "WD_%=:\n\t}" :: "r"(_m), "r"(_p) : "memory");                       \
    }                                                                            \
} while (0)

// ---------------- prepass: fp32 -> permuted fp16 ----------------
__global__ __launch_bounds__(256)
void convert_kernel(const float* __restrict__ src, uint32_t* __restrict__ dst, int nrows) {
    int idx = blockIdx.x * 256 + threadIdx.x;
    if (idx >= nrows * 256) return;
    int r  = idx >> 8;
    int c8 = idx & 255;
    int kb = c8 >> 3;
    int c  = c8 & 7;
    float4 v = *(const float4*)(src + ((size_t)r << 10) + kb * 32 + c * 4);
    uint32_t h01 = pack_h2(v.x, v.y);
    uint32_t h23 = pack_h2(v.z, v.w);
    size_t base = ((size_t)r * 32 + kb) * 16;
    int p0 = 8 * (c & 1) + (c >> 1);
    dst[base + p0]     = h01;
    dst[base + p0 + 4] = h23;
}

// ---------------- hterm = hx @ W_hh^T + b_ih + b_hh (fp32 exact) ----------------
__global__ __launch_bounds__(256)
void hterm_kernel(const float* __restrict__ hx, const float* __restrict__ Whh,
                  const float* __restrict__ bih, const float* __restrict__ bhh) {
    int gw   = (blockIdx.x * blockDim.x + threadIdx.x) >> 5;
    int lane = threadIdx.x & 31;
    if (gw >= H_DIM) return;
    int h = gw;

    float acc[B_DIM];
#pragma unroll
    for (int b = 0; b < B_DIM; ++b) acc[b] = 0.0f;

    const float4* wr = (const float4*)(Whh + (size_t)h * H_DIM);
#pragma unroll
    for (int it = 0; it < H_DIM / 128; ++it) {
        int j = lane + it * 32;
        float4 w4 = wr[j];
#pragma unroll
        for (int b = 0; b < B_DIM; ++b) {
            float4 hv = ((const float4*)(hx + (size_t)b * H_DIM))[j];
            acc[b] += w4.x * hv.x + w4.y * hv.y + w4.z * hv.z + w4.w * hv.w;
        }
    }
#pragma unroll
    for (int b = 0; b < B_DIM; ++b)
#pragma unroll
        for (int o = 16; o > 0; o >>= 1)
            acc[b] += __shfl_xor_sync(0xFFFFFFFFu, acc[b], o);

    if (lane == 0) {
        float bias = bih[h] + bhh[h];
#pragma unroll
        for (int b = 0; b < B_DIM; ++b)
            g_hterm[b * H_DIM + h] = acc[b] + bias;
    }
}

// ---------------- main GEMM + tanh: warp-specialized mbarrier pipeline ------
// 16 consumer warps (8 M x 2 N, warp tile 32x64) + 1 producer warp.
// Producer signals FULL(s) with plain mbarrier.arrive (32 lane arrivals) only
// AFTER cp.async.wait_group proves that tile's copy group completed.
// Consumers: wait FULL(t&3) parity (t>>2)&1; lane0 arrives EMPTY (count 16).
// No __syncthreads in the main loop -> consumer warps de-phase.
__global__ __launch_bounds__(THREADS, 1)
void gemm_tanh_kernel(float* __restrict__ out) {
    extern __shared__ __align__(16) uint32_t sbuf[];

    int tid  = threadIdx.x;
    int wid  = tid >> 5;
    int lane = tid & 31;

    int mb = blockIdx.x >> 3;
    int nb = blockIdx.x & 7;           // 8 consecutive CTAs share x M-tile in L2
    int m0 = mb * BM;
    int n0 = nb * BN;
    int bb = m0 >> 11;

    uint32_t sb = smem_u32(sbuf);
#define FULL_MB(s)  (sb + (s) * 8)
#define EMPTY_MB(s) (sb + 32 + (s) * 8)

    if (tid == 0) {
#pragma unroll
        for (int s = 0; s < 4; ++s) {
            MBARRIER_INIT(FULL_MB(s), 32);   // 32 producer lanes
            MBARRIER_INIT(EMPTY_MB(s), 16);  // 16 consumer warps (lane0)
        }
    }
    __syncthreads();   // the ONLY CTA-wide barrier

    if (wid == 16) {
        // ================= producer warp =================
        int rowb = lane >> 2;          // 0..7
        int sub  = lane & 3;           // 16B chunk in 64B row
        const uint32_t* srcA = g_xh + (size_t)(m0 + rowb) * 512 + sub * 4;
        const uint32_t* srcB = g_wh + (size_t)(n0 + rowb) * 512 + sub * 4;
        uint32_t dA = sb + 128 + (rowb * 16 + sub * 4) * 4;
        uint32_t dB = dA + 16384;

#define PCOPY(tofs, soff) do {                                                   \
        const uint32_t* _a = srcA + (tofs);                                      \
        const uint32_t* _b = srcB + (tofs);                                      \
        uint32_t _da = dA + (soff), _db = dB + (soff);                           \
        _Pragma("unroll")                                                        \
        for (int i5 = 0; i5 < 32; ++i5)   /* A: rows rowb+8*i5, 256 rows */      \
            CP16(_da + i5 * 512, _a + (size_t)i5 * 4096);                        \
        _Pragma("unroll")                                                        \
        for (int i5 = 0; i5 < 16; ++i5)   /* B: rows rowb+8*i5, 128 rows */      \
            CP16(_db + i5 * 512, _b + (size_t)i5 * 4096);                        \
    } while (0)

        // prologue: tiles 0,1,2 issued; distance-2 completion signaling
        PCOPY(0, 0);                  CP_COMMIT();
        PCOPY(16, STAGE_BYTES);       CP_COMMIT();
        PCOPY(32, 2 * STAGE_BYTES);   CP_COMMIT();
        CP_WAITG(2);  MBARRIER_ARRIVE(FULL_MB(0));     // tile 0 done
        PCOPY(48, 3 * STAGE_BYTES);   CP_COMMIT();
        CP_WAITG(2);  MBARRIER_ARRIVE(FULL_MB(1));     // tile 1 done

        // main: tiles 4..31; before overwriting stage s (use k=t>>2) wait
        // EMPTY parity (k-1)&1; after commit, signal tile t-2 complete.
        for (int t = 4; t < KIT; ++t) {
            int s = t & 3;
            uint32_t epar = ((t >> 2) - 1) & 1;
            MBARRIER_WAIT_PARITY(EMPTY_MB(s), epar);
            PCOPY(t * 16, s * STAGE_BYTES);
            CP_COMMIT();
            CP_WAITG(2);
            MBARRIER_ARRIVE(FULL_MB((t - 2) & 3));
        }
        // tail: tiles 30, 31
        CP_WAITG(1);  MBARRIER_ARRIVE(FULL_MB(2));     // tile 30 (30&3=2)
        CP_WAITG(0);  MBARRIER_ARRIVE(FULL_MB(3));     // tile 31 (31&3=3)
    } else {
        // ================= consumer warps =================
        int g  = lane >> 2;
        int tg = lane & 3;
        int warp_m = (wid & 7) * 32;       // 8 warps along M (256 rows)
        int warp_n = (wid >> 3) * 64;      // 2 warps along N (128 cols)

        float acc[2][8][4];
#pragma unroll
        for (int mt = 0; mt < 2; ++mt)
#pragma unroll
            for (int nt = 0; nt < 8; ++nt)
#pragma unroll
                for (int r = 0; r < 4; ++r) acc[mt][nt][r] = 0.0f;

        for (int tb = 0; tb < 4; ++tb) {
#pragma unroll
            for (int j = 0; j < 8; ++j) {          // tile t = tb*8 + j
                const int s   = j & 3;             // stage (compile-time)
                const int par = (j >> 2) & 1;      // (t>>2)&1 == (j>>2)&1
                MBARRIER_WAIT_PARITY(FULL_MB(s), par);

                const uint32_t* stg = sbuf + 32 + s * STAGE_U32;   // +128B
                const uint32_t* sBp = stg + 4096;                  // B at +16KB

                int R = warp_m + g;
                uint4 aL0 = *(const uint4*)(stg + R * 16 + 4 * tg);
                uint4 aH0 = *(const uint4*)(stg + (R + 8) * 16 + 4 * tg);
                uint4 aL1 = *(const uint4*)(stg + (R + 16) * 16 + 4 * tg);
                uint4 aH1 = *(const uint4*)(stg + (R + 24) * 16 + 4 * tg);

#pragma unroll
                for (int nt = 0; nt < 8; ++nt) {
                    uint4 bv = *(const uint4*)(sBp + (warp_n + nt * 8 + g) * 16 + 4 * tg);
                    mma16816(acc[0][nt], aL0.x, aH0.x, aL0.y, aH0.y, bv.x, bv.y);
                    mma16816(acc[0][nt], aL0.z, aH0.z, aL0.w, aH0.w, bv.z, bv.w);
                    mma16816(acc[1][nt], aL1.x, aH1.x, aL1.y, aH1.y, bv.x, bv.y);
                    mma16816(acc[1][nt], aL1.z, aH1.z, aL1.w, aH1.w, bv.z, bv.w);
                }
                if (lane == 0) MBARRIER_ARRIVE(EMPTY_MB(s));
            }
        }

        // ---- epilogue: +hterm, tanh, store ----
        const float* ht = g_hterm + bb * H_DIM + n0;
#pragma unroll
        for (int mt = 0; mt < 2; ++mt) {
            int r0 = m0 + warp_m + mt * 16 + g;
#pragma unroll
            for (int nt = 0; nt < 8; ++nt) {
                int nloc = warp_n + nt * 8 + tg * 2;
                float h0 = __ldg(ht + nloc), h1 = __ldg(ht + nloc + 1);
                float* a = acc[mt][nt];
                float2 v0, v1;
                v0.x = tanh_fast(a[0] + h0);
                v0.y = tanh_fast(a[1] + h1);
                v1.x = tanh_fast(a[2] + h0);
                v1.y = tanh_fast(a[3] + h1);
                *(float2*)(out + (size_t)r0 * H_DIM + n0 + nloc) = v0;
                *(float2*)(out + (size_t)(r0 + 8) * H_DIM + n0 + nloc) = v1;
            }
        }
    }
}

// ---------------- launch ----------------
extern "C" void kernel_launch(void* const* d_in, const int* in_sizes, int n_in,
                              void* d_out, int out_size) {
    const float* x   = (const float*)d_in[0];
    const float* hx  = (const float*)d_in[1];
    const float* Wih = (const float*)d_in[2];
    const float* Whh = (const float*)d_in[3];
    const float* bih = (const float*)d_in[4];
    const float* bhh = (const float*)d_in[5];
    float* out = (float*)d_out;

    uint32_t* xh;  cudaGetSymbolAddress((void**)&xh, g_xh);
    uint32_t* wh;  cudaGetSymbolAddress((void**)&wh, g_wh);

    cudaFuncSetAttribute(gemm_tanh_kernel,
                         cudaFuncAttributeMaxDynamicSharedMemorySize, SMEM_BYTES);

    convert_kernel<<<(M_TOTAL * 256) / 256, 256>>>(x,   xh, M_TOTAL);
    convert_kernel<<<(H_DIM  * 256) / 256, 256>>>(Wih, wh, H_DIM);
    hterm_kernel<<<H_DIM / 8, 256>>>(hx, Whh, bih, bhh);
    gemm_tanh_kernel<<<(M_TOTAL / BM) * (H_DIM / BN), THREADS, SMEM_BYTES>>>(out);
}